// round 5
// baseline (speedup 1.0000x reference)
#include <cuda_runtime.h>
#include <math.h>

#define BB   4
#define TLEN 32768
#define NM   80
#define RC   120
#define SC   240
#define NBLK 16
#define NC   256
#define TT   64

// ---------------- device scratch (no allocations allowed) ----------------
__device__ float g_resA[BB * RC * TLEN];     // 62.9 MB
__device__ float g_resB[BB * RC * TLEN];     // 62.9 MB
__device__ float g_skip[BB * SC * TLEN];     // 125.8 MB
__device__ float g_o[BB * NC * TLEN];        // 134.2 MB (head intermediate)
__device__ float g_W1[NBLK * 320 * 240];     // phase-1 weights, [i][k][c]
__device__ float g_W2[NBLK * 120 * 360];     // phase-2 weights, [i][k][c] (skip||res)
__device__ float g_Wo[240 * 256];            // out_w transposed: [k][o]
__device__ float g_We[256 * 256];            // end_w transposed: [k][o]

// ---------------- weight repack kernels ----------------------------------
__global__ void repack_w1(const float* __restrict__ dil_w,
                          const float* __restrict__ cond_w) {
    int idx = blockIdx.x * blockDim.x + threadIdx.x;
    const int total = NBLK * 320 * 240;
    if (idx >= total) return;
    int c = idx % 240;
    int k = (idx / 240) % 320;
    int i = idx / (240 * 320);
    float w;
    if (k < 120)       w = dil_w[((i * 240 + c) * 120 + k) * 2 + 0];
    else if (k < 240)  w = dil_w[((i * 240 + c) * 120 + (k - 120)) * 2 + 1];
    else               w = cond_w[(i * 240 + c) * 80 + (k - 240)];
    g_W1[idx] = w;
}

__global__ void repack_w2(const float* __restrict__ skip_w,
                          const float* __restrict__ res_w) {
    int idx = blockIdx.x * blockDim.x + threadIdx.x;
    const int total = NBLK * 120 * 360;
    if (idx >= total) return;
    int c = idx % 360;
    int k = (idx / 360) % 120;
    int i = idx / (360 * 120);
    float w = (c < 240) ? skip_w[(i * 240 + c) * 120 + k]
                        : res_w[(i * 120 + (c - 240)) * 120 + k];
    g_W2[idx] = w;
}

__global__ void repack_wf(const float* __restrict__ out_w,
                          const float* __restrict__ end_w) {
    int idx = blockIdx.x * blockDim.x + threadIdx.x;
    if (idx < 240 * 256) {
        int k = idx / 256, o = idx % 256;
        g_Wo[idx] = out_w[o * 240 + k];
    } else if (idx < 240 * 256 + 256 * 256) {
        int j = idx - 240 * 256;
        int k = j / 256, o = j % 256;
        g_We[j] = end_w[o * 256 + k];
    }
}

// ---------------- prologue: res0 = wav_w * wav + wav_b -------------------
__global__ void prologue_kernel(const float* __restrict__ wav,
                                const float* __restrict__ wav_w,
                                const float* __restrict__ wav_b) {
    int idx = blockIdx.x * blockDim.x + threadIdx.x;
    const int total = BB * RC * TLEN;
    if (idx >= total) return;
    int t = idx % TLEN;
    int c = (idx / TLEN) % RC;
    int b = idx / (TLEN * RC);
    g_resA[idx] = wav_w[c] * wav[b * TLEN + t] + wav_b[c];
}

// fast, saturation-safe activations
__device__ __forceinline__ float fast_tanh(float x) {
    return 1.f - 2.f / (1.f + __expf(2.f * x));
}
__device__ __forceinline__ float fast_sigmoid(float x) {
    return 1.f / (1.f + __expf(-x));
}

// ---------------- per-block fused kernel (192 threads, static smem) ------
// smem: sout[120*65] (31.2KB) | Ws[8*360] (11.25KB) | Bs[8*64] (2KB) = 44.7KB
__global__ void __launch_bounds__(192, 2) block_kernel(
    const float* __restrict__ cond,
    const float* __restrict__ dil_b, const float* __restrict__ cond_b,
    const float* __restrict__ skip_b, const float* __restrict__ res_b,
    int i, int d, int first, int swap)
{
    __shared__ float sout[120 * 65];
    __shared__ float Ws[8 * 360];
    __shared__ float Bs[8 * 64];

    const float* __restrict__ resIn  = swap ? g_resB : g_resA;
    float* __restrict__       resOut = swap ? g_resA : g_resB;

    const int tid = threadIdx.x;
    const int tx = tid & 15;              // t group (16)
    const int ty = tid >> 4;              // c group (12)
    const int t0 = blockIdx.x * TT;
    const int b  = blockIdx.y;

    // ---- phase 1: g[240 x 64] = W1 @ [res_shift; res; cond] ----
    // thread owns tanh channels ct = ty + 12*j (j<10) and paired sigmoid
    // channels ct+120, gated in registers afterward.
    float at[10][4], asg[10][4];
    #pragma unroll
    for (int j = 0; j < 10; j++) {
        int ct = ty + 12 * j;
        float bt = dil_b[i * 240 + ct]       + cond_b[i * 240 + ct];
        float bs = dil_b[i * 240 + ct + 120] + cond_b[i * 240 + ct + 120];
        #pragma unroll
        for (int m = 0; m < 4; m++) { at[j][m] = bt; asg[j][m] = bs; }
    }

    for (int kc = 0; kc < 40; kc++) {
        int kb = kc * 8;
        __syncthreads();
        // stage activations [8][64]
        for (int e = tid; e < 8 * 64; e += 192) {
            int kk = e >> 6, tt = e & 63;
            int k = kb + kk;
            float v;
            if (k < 120) {
                int gt = t0 + tt - d;
                v = (gt >= 0) ? resIn[(b * RC + k) * TLEN + gt] : 0.f;
            } else if (k < 240) {
                v = resIn[(b * RC + (k - 120)) * TLEN + t0 + tt];
            } else {
                v = cond[(b * NM + (k - 240)) * TLEN + t0 + tt];
            }
            Bs[e] = v;
        }
        // stage weights [8][240] (coalesced thanks to repack)
        for (int e = tid; e < 8 * 240; e += 192)
            Ws[e] = g_W1[(i * 320 + kb) * 240 + e];
        __syncthreads();
        #pragma unroll
        for (int kk = 0; kk < 8; kk++) {
            float a0 = Bs[kk * 64 + tx];
            float a1 = Bs[kk * 64 + tx + 16];
            float a2 = Bs[kk * 64 + tx + 32];
            float a3 = Bs[kk * 64 + tx + 48];
            const float* wr = &Ws[kk * 240 + ty];
            #pragma unroll
            for (int j = 0; j < 10; j++) {
                float wt = wr[12 * j];
                float ws = wr[12 * j + 120];
                at[j][0]  += wt * a0; at[j][1]  += wt * a1;
                at[j][2]  += wt * a2; at[j][3]  += wt * a3;
                asg[j][0] += ws * a0; asg[j][1] += ws * a1;
                asg[j][2] += ws * a2; asg[j][3] += ws * a3;
            }
        }
    }

    // ---- gating in registers -> sout[120][64] ----
    __syncthreads();
    #pragma unroll
    for (int j = 0; j < 10; j++) {
        int ct = ty + 12 * j;
        #pragma unroll
        for (int m = 0; m < 4; m++) {
            float v = fast_tanh(at[j][m]) * fast_sigmoid(asg[j][m]);
            sout[ct * 65 + tx + 16 * m] = v;
        }
    }
    // phase-2 loop's first __syncthreads orders these writes before reads

    // ---- phase 2: [skip(240) || res(120)] x 64, K = 120 ----
    for (int half = 0; half < 2; half++) {
        float acc2[30][2];
        #pragma unroll
        for (int j = 0; j < 30; j++) {
            int c = ty + 12 * j;
            float bias = (c < 240) ? skip_b[i * 240 + c]
                                   : res_b[i * 120 + (c - 240)];
            acc2[j][0] = bias; acc2[j][1] = bias;
        }
        for (int kc = 0; kc < 15; kc++) {
            int kb = kc * 8;
            __syncthreads();
            for (int e = tid; e < 8 * 360; e += 192)
                Ws[e] = g_W2[(i * 120 + kb) * 360 + e];
            __syncthreads();
            #pragma unroll
            for (int kk = 0; kk < 8; kk++) {
                float a0 = sout[(kb + kk) * 65 + tx + 32 * half];
                float a1 = sout[(kb + kk) * 65 + tx + 32 * half + 16];
                const float* wr = &Ws[kk * 360 + ty];
                #pragma unroll
                for (int j = 0; j < 30; j++) {
                    float w = wr[12 * j];
                    acc2[j][0] += w * a0; acc2[j][1] += w * a1;
                }
            }
        }
        // epilogue
        #pragma unroll
        for (int j = 0; j < 30; j++) {
            int c = ty + 12 * j;
            #pragma unroll
            for (int m = 0; m < 2; m++) {
                int gt = t0 + tx + 16 * m + 32 * half;
                if (c < 240) {
                    int idx = (b * SC + c) * TLEN + gt;
                    if (first) g_skip[idx] = acc2[j][m];
                    else       g_skip[idx] += acc2[j][m];
                } else {
                    int idx = (b * RC + (c - 240)) * TLEN + gt;
                    resOut[idx] = acc2[j][m] + resIn[idx];
                }
            }
        }
    }
}

// ---------------- head kernel 1: o = out_w @ relu(skip) + out_b ----------
__global__ void __launch_bounds__(256, 2) final1_kernel(
    const float* __restrict__ out_b)
{
    __shared__ float Ws[8 * 256];
    __shared__ float Bs[8 * 64];

    const int tid = threadIdx.x;
    const int tx = tid & 15, ty = tid >> 4;
    const int t0 = blockIdx.x * TT;
    const int b  = blockIdx.y;

    float acc[16][4];
    #pragma unroll
    for (int j = 0; j < 16; j++) {
        float bv = out_b[ty + 16 * j];
        #pragma unroll
        for (int m = 0; m < 4; m++) acc[j][m] = bv;
    }
    for (int kc = 0; kc < 30; kc++) {
        int kb = kc * 8;
        __syncthreads();
        for (int e = tid; e < 8 * 64; e += 256) {
            int kk = e >> 6, tt = e & 63;
            float v = g_skip[(b * SC + kb + kk) * TLEN + t0 + tt];
            Bs[e] = fmaxf(v, 0.f);
        }
        for (int e = tid; e < 8 * 256; e += 256)
            Ws[e] = g_Wo[kb * 256 + e];
        __syncthreads();
        #pragma unroll
        for (int kk = 0; kk < 8; kk++) {
            float a0 = Bs[kk * 64 + tx];
            float a1 = Bs[kk * 64 + tx + 16];
            float a2 = Bs[kk * 64 + tx + 32];
            float a3 = Bs[kk * 64 + tx + 48];
            const float* wr = &Ws[kk * 256 + ty];
            #pragma unroll
            for (int j = 0; j < 16; j++) {
                float w = wr[16 * j];
                acc[j][0] += w * a0; acc[j][1] += w * a1;
                acc[j][2] += w * a2; acc[j][3] += w * a3;
            }
        }
    }
    #pragma unroll
    for (int j = 0; j < 16; j++) {
        int o = ty + 16 * j;
        #pragma unroll
        for (int m = 0; m < 4; m++)
            g_o[(b * NC + o) * TLEN + t0 + tx + 16 * m] = acc[j][m];
    }
}

// ---------------- head kernel 2: end = end_w @ relu(o) + end_b -----------
__global__ void __launch_bounds__(256, 2) final2_kernel(
    const float* __restrict__ end_b, float* __restrict__ out)
{
    __shared__ float Ws[8 * 256];
    __shared__ float Bs[8 * 64];

    const int tid = threadIdx.x;
    const int tx = tid & 15, ty = tid >> 4;
    const int t0 = blockIdx.x * TT;
    const int b  = blockIdx.y;

    float acc[16][4];
    #pragma unroll
    for (int j = 0; j < 16; j++) {
        float bv = end_b[ty + 16 * j];
        #pragma unroll
        for (int m = 0; m < 4; m++) acc[j][m] = bv;
    }
    for (int kc = 0; kc < 32; kc++) {
        int kb = kc * 8;
        __syncthreads();
        for (int e = tid; e < 8 * 64; e += 256) {
            int kk = e >> 6, tt = e & 63;
            float v = g_o[(b * NC + kb + kk) * TLEN + t0 + tt];
            Bs[e] = fmaxf(v, 0.f);
        }
        for (int e = tid; e < 8 * 256; e += 256)
            Ws[e] = g_We[kb * 256 + e];
        __syncthreads();
        #pragma unroll
        for (int kk = 0; kk < 8; kk++) {
            float a0 = Bs[kk * 64 + tx];
            float a1 = Bs[kk * 64 + tx + 16];
            float a2 = Bs[kk * 64 + tx + 32];
            float a3 = Bs[kk * 64 + tx + 48];
            const float* wr = &Ws[kk * 256 + ty];
            #pragma unroll
            for (int j = 0; j < 16; j++) {
                float w = wr[16 * j];
                acc[j][0] += w * a0; acc[j][1] += w * a1;
                acc[j][2] += w * a2; acc[j][3] += w * a3;
            }
        }
    }
    #pragma unroll
    for (int j = 0; j < 16; j++) {
        int o = ty + 16 * j;
        #pragma unroll
        for (int m = 0; m < 4; m++)
            out[(b * NC + o) * TLEN + t0 + tx + 16 * m] = acc[j][m];
    }
}

// ---------------- host launcher ------------------------------------------
extern "C" void kernel_launch(void* const* d_in, const int* in_sizes, int n_in,
                              void* d_out, int out_size) {
    const float* wav    = (const float*)d_in[0];
    const float* cond   = (const float*)d_in[1];
    const float* wav_w  = (const float*)d_in[2];
    const float* wav_b  = (const float*)d_in[3];
    const float* cond_w = (const float*)d_in[4];
    const float* cond_b = (const float*)d_in[5];
    const float* dil_w  = (const float*)d_in[6];
    const float* dil_b  = (const float*)d_in[7];
    const float* skip_w = (const float*)d_in[8];
    const float* skip_b = (const float*)d_in[9];
    const float* res_w  = (const float*)d_in[10];
    const float* res_b  = (const float*)d_in[11];
    const float* out_w  = (const float*)d_in[12];
    const float* out_b  = (const float*)d_in[13];
    const float* end_w  = (const float*)d_in[14];
    const float* end_b  = (const float*)d_in[15];

    repack_w1<<<(NBLK * 320 * 240 + 255) / 256, 256>>>(dil_w, cond_w);
    repack_w2<<<(NBLK * 120 * 360 + 255) / 256, 256>>>(skip_w, res_w);
    repack_wf<<<(240 * 256 + 256 * 256 + 255) / 256, 256>>>(out_w, end_w);
    prologue_kernel<<<(BB * RC * TLEN + 255) / 256, 256>>>(wav, wav_w, wav_b);

    dim3 grid(TLEN / TT, BB);
    for (int i = 0; i < NBLK; i++) {
        int d = 1 << (i % 8);
        block_kernel<<<grid, 192>>>(cond, dil_b, cond_b, skip_b, res_b,
                                    i, d, (i == 0) ? 1 : 0, i & 1);
    }
    final1_kernel<<<grid, 256>>>(out_b);
    final2_kernel<<<grid, 256>>>(end_b, (float*)d_out);
}

// round 7
// speedup vs baseline: 2.3399x; 2.3399x over previous
#include <cuda_runtime.h>
#include <cuda_bf16.h>
#include <math.h>
#include <stdint.h>

#define BB   4
#define TLEN 32768
#define NM   80
#define RC   120
#define SC   240
#define NBLK 16
#define NC   256

// ---------------- device scratch (no allocations allowed) ----------------
// res / cond as bf16 hi/lo, layout [b][t][128c] (row = 256B = 16 uint4)
__device__ uint4 g_resAH[BB * TLEN * 16];
__device__ uint4 g_resAL[BB * TLEN * 16];
__device__ uint4 g_resBH[BB * TLEN * 16];
__device__ uint4 g_resBL[BB * TLEN * 16];
__device__ uint4 g_condH[BB * TLEN * 16];
__device__ uint4 g_condL[BB * TLEN * 16];
__device__ float g_skip [BB * TLEN * SC];   // [b][t][c]
__device__ float g_skipT[BB * SC * TLEN];   // [b][c][t]
__device__ float g_o    [BB * NC * TLEN];
// weights as pre-swizzled smem tile images ([rows][64k] bf16, 128B rows)
__device__ uint4 g_W1h[NBLK * 6 * 1920];    // phase1, rows = permuted n (240)
__device__ uint4 g_W1l[NBLK * 6 * 1920];
__device__ uint4 g_W2sh[NBLK * 2 * 1920];   // skip [240][64]
__device__ uint4 g_W2sl[NBLK * 2 * 1920];
__device__ uint4 g_W2rh[NBLK * 2 * 960];    // res  [120][64]
__device__ uint4 g_W2rl[NBLK * 2 * 960];
__device__ float g_Wo[240 * 256];           // out_w transposed [k][o]
__device__ float g_We[256 * 256];           // end_w transposed [k][o]

// ---------------- helpers -------------------------------------------------
__device__ __forceinline__ uint32_t smem_u32(const void* p) {
    uint32_t a;
    asm("{ .reg .u64 t; cvta.to.shared.u64 t, %1; cvt.u32.u64 %0, t; }"
        : "=r"(a) : "l"(p));
    return a;
}
__device__ __forceinline__ uint32_t sw128(uint32_t b) { return b ^ ((b >> 3) & 0x70); }

union U4B { uint4 u; __nv_bfloat16 h[8]; };
union U1B { uint32_t u; __nv_bfloat16 h[2]; };

__device__ __forceinline__ void split_bf16(float x, __nv_bfloat16& hi, __nv_bfloat16& lo) {
    hi = __float2bfloat16(x);
    lo = __float2bfloat16(x - __bfloat162float(hi));
}
__device__ __forceinline__ float fast_tanh(float x) {
    return 1.f - 2.f / (1.f + __expf(2.f * x));
}
__device__ __forceinline__ float fast_sigmoid(float x) {
    return 1.f / (1.f + __expf(-x));
}

__device__ __forceinline__ void ldsm_x4(uint32_t* r, uint32_t addr) {
    asm volatile("ldmatrix.sync.aligned.m8n8.x4.shared.b16 {%0,%1,%2,%3}, [%4];"
                 : "=r"(r[0]), "=r"(r[1]), "=r"(r[2]), "=r"(r[3]) : "r"(addr));
}
__device__ __forceinline__ void ldsm_x2(uint32_t* r, uint32_t addr) {
    asm volatile("ldmatrix.sync.aligned.m8n8.x2.shared.b16 {%0,%1}, [%2];"
                 : "=r"(r[0]), "=r"(r[1]) : "r"(addr));
}
__device__ __forceinline__ void mma16816(float* c, const uint32_t* a,
                                         uint32_t b0, uint32_t b1) {
    asm volatile("mma.sync.aligned.m16n8k16.row.col.f32.bf16.bf16.f32 "
                 "{%0,%1,%2,%3}, {%4,%5,%6,%7}, {%8,%9}, {%0,%1,%2,%3};"
                 : "+f"(c[0]), "+f"(c[1]), "+f"(c[2]), "+f"(c[3])
                 : "r"(a[0]), "r"(a[1]), "r"(a[2]), "r"(a[3]), "r"(b0), "r"(b1));
}

// ---------------- weight repack kernels -----------------------------------
// phase1: rows n permuted: n=2p -> tanh channel p; n=2p+1 -> sigmoid p (=p+120)
__global__ void repack_w1(const float* __restrict__ dil_w,
                          const float* __restrict__ cond_w) {
    int idx = blockIdx.x * blockDim.x + threadIdx.x;
    const int total = NBLK * 6 * 240 * 64;
    if (idx >= total) return;
    int kk = idx & 63;
    int n  = (idx >> 6) % 240;
    int q  = (idx / (64 * 240)) % 6;
    int i  = idx / (64 * 240 * 6);
    int c  = (n >> 1) + (n & 1) * 120;          // original output channel
    int kc = (q & 1) * 64 + kk;
    float w = 0.f;
    if (q < 2)      { if (kc < 120) w = dil_w[((i*240 + c)*120 + kc)*2 + 0]; }
    else if (q < 4) { if (kc < 120) w = dil_w[((i*240 + c)*120 + kc)*2 + 1]; }
    else            { if (kc < 80)  w = cond_w[(i*240 + c)*80 + kc]; }
    __nv_bfloat16 hi, lo; split_bf16(w, hi, lo);
    int elem = sw128(n * 128 + kk * 2) >> 1;
    size_t base = (size_t)(i * 6 + q) * 15360;
    ((__nv_bfloat16*)g_W1h)[base + elem] = hi;
    ((__nv_bfloat16*)g_W1l)[base + elem] = lo;
}

__global__ void repack_w2(const float* __restrict__ skip_w,
                          const float* __restrict__ res_w) {
    int idx = blockIdx.x * blockDim.x + threadIdx.x;
    const int totS = NBLK * 2 * 240 * 64;
    const int totR = NBLK * 2 * 120 * 64;
    if (idx < totS) {
        int kk = idx & 63;
        int c  = (idx >> 6) % 240;
        int q  = (idx / (64 * 240)) % 2;
        int i  = idx / (64 * 240 * 2);
        int k  = q * 64 + kk;
        float w = (k < 120) ? skip_w[(i*240 + c)*120 + k] : 0.f;
        __nv_bfloat16 hi, lo; split_bf16(w, hi, lo);
        int elem = sw128(c * 128 + kk * 2) >> 1;
        size_t base = (size_t)(i * 2 + q) * 15360;
        ((__nv_bfloat16*)g_W2sh)[base + elem] = hi;
        ((__nv_bfloat16*)g_W2sl)[base + elem] = lo;
    } else if (idx < totS + totR) {
        int j = idx - totS;
        int kk = j & 63;
        int c  = (j >> 6) % 120;
        int q  = (j / (64 * 120)) % 2;
        int i  = j / (64 * 120 * 2);
        int k  = q * 64 + kk;
        float w = (k < 120) ? res_w[(i*120 + c)*120 + k] : 0.f;
        __nv_bfloat16 hi, lo; split_bf16(w, hi, lo);
        int elem = sw128(c * 128 + kk * 2) >> 1;
        size_t base = (size_t)(i * 2 + q) * 7680;
        ((__nv_bfloat16*)g_W2rh)[base + elem] = hi;
        ((__nv_bfloat16*)g_W2rl)[base + elem] = lo;
    }
}

__global__ void repack_wf(const float* __restrict__ out_w,
                          const float* __restrict__ end_w) {
    int idx = blockIdx.x * blockDim.x + threadIdx.x;
    if (idx < 240 * 256) {
        int k = idx / 256, o = idx % 256;
        g_Wo[idx] = out_w[o * 240 + k];
    } else if (idx < 240 * 256 + 256 * 256) {
        int j = idx - 240 * 256;
        int k = j / 256, o = j % 256;
        g_We[j] = end_w[o * 256 + k];
    }
}

// ---------------- prologues -----------------------------------------------
__global__ void prologue_res(const float* __restrict__ wav,
                             const float* __restrict__ wav_w,
                             const float* __restrict__ wav_b) {
    int idx = blockIdx.x * blockDim.x + threadIdx.x;
    const int total = BB * TLEN * 16;
    if (idx >= total) return;
    int chunk = idx & 15;
    int t = (idx >> 4) % TLEN;
    int b = idx / (TLEN * 16);
    float wv = wav[(size_t)b * TLEN + t];
    U4B uh, ul;
    #pragma unroll
    for (int e = 0; e < 8; e++) {
        int c = chunk * 8 + e;
        float v = (c < RC) ? (wav_w[c] * wv + wav_b[c]) : 0.f;
        split_bf16(v, uh.h[e], ul.h[e]);
    }
    g_resAH[idx] = uh.u;
    g_resAL[idx] = ul.u;
}

__global__ void prologue_cond(const float* __restrict__ cond) {
    int idx = blockIdx.x * blockDim.x + threadIdx.x;
    const int total = BB * TLEN * 16;
    if (idx >= total) return;
    int chunk = idx & 15;
    int t = (idx >> 4) % TLEN;
    int b = idx / (TLEN * 16);
    U4B uh, ul;
    #pragma unroll
    for (int e = 0; e < 8; e++) {
        int c = chunk * 8 + e;
        float v = (c < NM) ? cond[((size_t)b * NM + c) * TLEN + t] : 0.f;
        split_bf16(v, uh.h[e], ul.h[e]);
    }
    g_condH[idx] = uh.u;
    g_condL[idx] = ul.u;
}

// ---------------- mma per-layer kernel ------------------------------------
// dynamic smem (bytes)
#define OFF_BA   0        // 240 floats
#define OFF_BB   1024     // 360 floats
#define OFF_XH   4096     // [128][64] bf16 = 16384
#define OFF_XL   20480
#define OFF_WH   36864    // [240][64] bf16 = 30720
#define OFF_WL   67584
#define OFF_RH   98304    // [2][120][64] bf16 = 30720
#define OFF_RL   129024
#define OFF_A2H  159744   // [2][128][64] bf16 = 32768
#define OFF_A2L  192512
#define SMEM_MMA 225280

__global__ void __launch_bounds__(256, 1) block_mma(
    const float* __restrict__ dil_b, const float* __restrict__ cond_b,
    const float* __restrict__ skip_b, const float* __restrict__ res_b,
    int layer, int d, int first, int swap)
{
    extern __shared__ __align__(16) char sm[];
    const uint32_t smb = smem_u32(sm);
    const int tid  = threadIdx.x;
    const int lane = tid & 31;
    const int wid  = tid >> 5;
    const int mw   = wid >> 1;            // 0..3 (m)
    const int nw   = wid & 1;             // 0..1 (n)
    const int b    = blockIdx.y;
    const int t0   = blockIdx.x * 128;

    const uint4* resInH = swap ? g_resBH : g_resAH;
    const uint4* resInL = swap ? g_resBL : g_resAL;
    uint4* resOutH = swap ? g_resAH : g_resBH;
    uint4* resOutL = swap ? g_resAL : g_resBL;

    float* biasA = (float*)(sm + OFF_BA);
    float* biasB = (float*)(sm + OFF_BB);
    for (int e = tid; e < 240; e += 256)
        biasA[e] = dil_b[layer * 240 + e] + cond_b[layer * 240 + e];
    for (int e = tid; e < 360; e += 256)
        biasB[e] = (e < 240) ? skip_b[layer * 240 + e] : res_b[layer * 120 + e - 240];
    // zero-pad phase2 A region B: k 56..63 (p 120..127)
    if (tid < 128) {
        uint32_t byte = tid * 128 + ((7u ^ (tid & 7)) << 4);
        *(uint4*)(sm + OFF_A2H + 16384 + byte) = make_uint4(0, 0, 0, 0);
        *(uint4*)(sm + OFF_A2L + 16384 + byte) = make_uint4(0, 0, 0, 0);
    }

    // ========== phase 1: g[128t x 240n(permuted)], K=384 ==========
    float ac[2][15][4];
    #pragma unroll
    for (int mt = 0; mt < 2; mt++)
        #pragma unroll
        for (int nt = 0; nt < 15; nt++)
            #pragma unroll
            for (int e = 0; e < 4; e++) ac[mt][nt][e] = 0.f;

    for (int q = 0; q < 6; q++) {
        __syncthreads();
        {   // stage X chunk [128][64] hi/lo
            const uint4* srcH; const uint4* srcL; int tshift, half;
            if (q < 2)      { srcH = resInH; srcL = resInL; tshift = t0 - d; half = q; }
            else if (q < 4) { srcH = resInH; srcL = resInL; tshift = t0;     half = q - 2; }
            else            { srcH = g_condH; srcL = g_condL; tshift = t0;   half = q - 4; }
            for (int e = tid; e < 1024; e += 256) {
                int r = e >> 3, ii = e & 7;
                int t = tshift + r;
                uint4 vh = make_uint4(0,0,0,0), vl = make_uint4(0,0,0,0);
                if (t >= 0) {
                    size_t si = ((size_t)b * TLEN + t) * 16 + half * 8 + ii;
                    vh = srcH[si]; vl = srcL[si];
                }
                uint32_t byte = sw128((r << 7) + (ii << 4));
                *(uint4*)(sm + OFF_XH + byte) = vh;
                *(uint4*)(sm + OFF_XL + byte) = vl;
            }
            size_t wb = (size_t)(layer * 6 + q) * 1920;
            for (int e = tid; e < 1920; e += 256) {
                ((uint4*)(sm + OFF_WH))[e] = g_W1h[wb + e];
                ((uint4*)(sm + OFF_WL))[e] = g_W1l[wb + e];
            }
        }
        __syncthreads();
        #pragma unroll
        for (int kt = 0; kt < 4; kt++) {
            uint32_t ah[2][4], al[2][4];
            #pragma unroll
            for (int mt = 0; mt < 2; mt++) {
                int ar = mw * 32 + mt * 16 + (lane & 15);
                int ack = kt * 2 + (lane >> 4);
                uint32_t ab = ar * 128 + (((uint32_t)(ack ^ (ar & 7))) << 4);
                ldsm_x4(ah[mt], smb + OFF_XH + ab);
                ldsm_x4(al[mt], smb + OFF_XL + ab);
            }
            int bn = nw * 120 + (lane & 7);
            int bsel = (lane >> 3) & 1;
            #pragma unroll
            for (int nt = 0; nt < 15; nt++) {
                int n = bn + nt * 8;
                int bck = kt * 2 + bsel;
                uint32_t bb = n * 128 + (((uint32_t)(bck ^ (n & 7))) << 4);
                uint32_t bh[2], bl[2];
                ldsm_x2(bh, smb + OFF_WH + bb);
                ldsm_x2(bl, smb + OFF_WL + bb);
                #pragma unroll
                for (int mt = 0; mt < 2; mt++) {
                    mma16816(ac[mt][nt], ah[mt], bh[0], bh[1]);
                    mma16816(ac[mt][nt], ah[mt], bl[0], bl[1]);
                    mma16816(ac[mt][nt], al[mt], bh[0], bh[1]);
                }
            }
        }
    }

    // ========== gating (in registers) -> phase2 A tile ==========
    #pragma unroll
    for (int nt = 0; nt < 15; nt++) {
        int p = nw * 60 + nt * 4 + (lane & 3);
        int reg = (p < 64) ? 0 : 1;
        int p2 = p & 63;
        float ba_t = biasA[p];
        float ba_s = biasA[p + 120];
        #pragma unroll
        for (int mt = 0; mt < 2; mt++) {
            #pragma unroll
            for (int rh = 0; rh < 2; rh++) {
                int r = mw * 32 + mt * 16 + (lane >> 2) + rh * 8;
                float gt = ac[mt][nt][rh * 2 + 0] + ba_t;
                float gs = ac[mt][nt][rh * 2 + 1] + ba_s;
                float v = fast_tanh(gt) * fast_sigmoid(gs);
                __nv_bfloat16 hi, lo; split_bf16(v, hi, lo);
                uint32_t byte = r * 128 + (((uint32_t)((p2 >> 3) ^ (r & 7))) << 4)
                              + (p2 & 7) * 2;
                *(__nv_bfloat16*)(sm + OFF_A2H + reg * 16384 + byte) = hi;
                *(__nv_bfloat16*)(sm + OFF_A2L + reg * 16384 + byte) = lo;
            }
        }
    }

    // ========== phase 2a: skip[128t x 240c], K=120 ==========
    float sk[2][15][4];
    #pragma unroll
    for (int mt = 0; mt < 2; mt++)
        #pragma unroll
        for (int nt = 0; nt < 15; nt++)
            #pragma unroll
            for (int e = 0; e < 4; e++) sk[mt][nt][e] = 0.f;

    for (int q2 = 0; q2 < 2; q2++) {
        __syncthreads();
        {
            size_t bs = (size_t)(layer * 2 + q2) * 1920;
            size_t br = (size_t)(layer * 2 + q2) * 960;
            for (int e = tid; e < 1920; e += 256) {
                ((uint4*)(sm + OFF_WH))[e] = g_W2sh[bs + e];
                ((uint4*)(sm + OFF_WL))[e] = g_W2sl[bs + e];
            }
            for (int e = tid; e < 960; e += 256) {
                ((uint4*)(sm + OFF_RH + q2 * 15360))[e] = g_W2rh[br + e];
                ((uint4*)(sm + OFF_RL + q2 * 15360))[e] = g_W2rl[br + e];
            }
        }
        __syncthreads();
        #pragma unroll
        for (int kt = 0; kt < 4; kt++) {
            uint32_t ah[2][4], al[2][4];
            #pragma unroll
            for (int mt = 0; mt < 2; mt++) {
                int ar = mw * 32 + mt * 16 + (lane & 15);
                int ack = kt * 2 + (lane >> 4);
                uint32_t ab = ar * 128 + (((uint32_t)(ack ^ (ar & 7))) << 4);
                ldsm_x4(ah[mt], smb + OFF_A2H + q2 * 16384 + ab);
                ldsm_x4(al[mt], smb + OFF_A2L + q2 * 16384 + ab);
            }
            int bn = nw * 120 + (lane & 7);
            int bsel = (lane >> 3) & 1;
            #pragma unroll
            for (int nt = 0; nt < 15; nt++) {
                int n = bn + nt * 8;
                int bck = kt * 2 + bsel;
                uint32_t bb = n * 128 + (((uint32_t)(bck ^ (n & 7))) << 4);
                uint32_t bh[2], bl[2];
                ldsm_x2(bh, smb + OFF_WH + bb);
                ldsm_x2(bl, smb + OFF_WL + bb);
                #pragma unroll
                for (int mt = 0; mt < 2; mt++) {
                    mma16816(sk[mt][nt], ah[mt], bh[0], bh[1]);
                    mma16816(sk[mt][nt], ah[mt], bl[0], bl[1]);
                    mma16816(sk[mt][nt], al[mt], bh[0], bh[1]);
                }
            }
        }
    }

    // skip epilogue: [b][t][240] fp32 accumulate
    #pragma unroll
    for (int nt = 0; nt < 15; nt++) {
        int c = nw * 120 + nt * 8 + 2 * (lane & 3);
        float b0 = biasB[c], b1 = biasB[c + 1];
        #pragma unroll
        for (int mt = 0; mt < 2; mt++) {
            #pragma unroll
            for (int rh = 0; rh < 2; rh++) {
                int t = t0 + mw * 32 + mt * 16 + (lane >> 2) + rh * 8;
                size_t gi = ((size_t)b * TLEN + t) * 240 + c;
                float2 v;
                v.x = sk[mt][nt][rh * 2 + 0] + b0;
                v.y = sk[mt][nt][rh * 2 + 1] + b1;
                if (!first) {
                    float2 o = *(float2*)(g_skip + gi);
                    v.x += o.x; v.y += o.y;
                }
                *(float2*)(g_skip + gi) = v;
            }
        }
    }

    // ========== phase 2b: res[128t x 120c], K=120 ==========
    {
        float rs[2][8][4];
        #pragma unroll
        for (int mt = 0; mt < 2; mt++)
            #pragma unroll
            for (int nt = 0; nt < 8; nt++)
                #pragma unroll
                for (int e = 0; e < 4; e++) rs[mt][nt][e] = 0.f;
        const int NT = 8 - nw;   // nw0: c 0-63 (8 tiles), nw1: 64-119 (7)

        for (int q2 = 0; q2 < 2; q2++) {
            #pragma unroll
            for (int kt = 0; kt < 4; kt++) {
                uint32_t ah[2][4], al[2][4];
                #pragma unroll
                for (int mt = 0; mt < 2; mt++) {
                    int ar = mw * 32 + mt * 16 + (lane & 15);
                    int ack = kt * 2 + (lane >> 4);
                    uint32_t ab = ar * 128 + (((uint32_t)(ack ^ (ar & 7))) << 4);
                    ldsm_x4(ah[mt], smb + OFF_A2H + q2 * 16384 + ab);
                    ldsm_x4(al[mt], smb + OFF_A2L + q2 * 16384 + ab);
                }
                int bn = nw * 64 + (lane & 7);
                int bsel = (lane >> 3) & 1;
                #pragma unroll
                for (int nt = 0; nt < 8; nt++) {
                    if (nt < NT) {
                        int n = bn + nt * 8;
                        int bck = kt * 2 + bsel;
                        uint32_t bb = n * 128 + (((uint32_t)(bck ^ (n & 7))) << 4);
                        uint32_t bh[2], bl[2];
                        ldsm_x2(bh, smb + OFF_RH + q2 * 15360 + bb);
                        ldsm_x2(bl, smb + OFF_RL + q2 * 15360 + bb);
                        #pragma unroll
                        for (int mt = 0; mt < 2; mt++) {
                            mma16816(rs[mt][nt], ah[mt], bh[0], bh[1]);
                            mma16816(rs[mt][nt], ah[mt], bl[0], bl[1]);
                            mma16816(rs[mt][nt], al[mt], bh[0], bh[1]);
                        }
                    }
                }
            }
        }

        // res epilogue: resOut = rs + bias + resIn(hi+lo), split back
        const uint32_t* rInH = (const uint32_t*)resInH;
        const uint32_t* rInL = (const uint32_t*)resInL;
        uint32_t* rOutH = (uint32_t*)resOutH;
        uint32_t* rOutL = (uint32_t*)resOutL;
        #pragma unroll
        for (int nt = 0; nt < 8; nt++) {
            if (nt < NT) {
                int c = nw * 64 + nt * 8 + 2 * (lane & 3);
                float b0 = biasB[240 + c], b1 = biasB[240 + c + 1];
                #pragma unroll
                for (int mt = 0; mt < 2; mt++) {
                    #pragma unroll
                    for (int rh = 0; rh < 2; rh++) {
                        int t = t0 + mw * 32 + mt * 16 + (lane >> 2) + rh * 8;
                        size_t ri = ((size_t)b * TLEN + t) * 64 + (c >> 1);
                        U1B vh, vl, oh, ol;
                        vh.u = rInH[ri]; vl.u = rInL[ri];
                        float o0 = rs[mt][nt][rh * 2 + 0] + b0
                                 + __bfloat162float(vh.h[0]) + __bfloat162float(vl.h[0]);
                        float o1 = rs[mt][nt][rh * 2 + 1] + b1
                                 + __bfloat162float(vh.h[1]) + __bfloat162float(vl.h[1]);
                        split_bf16(o0, oh.h[0], ol.h[0]);
                        split_bf16(o1, oh.h[1], ol.h[1]);
                        rOutH[ri] = oh.u;
                        rOutL[ri] = ol.u;
                    }
                }
            }
        }
    }
    // zero pad channels 120-127 of resOut
    if (tid < 128) {
        size_t rp = ((size_t)b * TLEN + t0 + tid) * 16 + 15;
        resOutH[rp] = make_uint4(0, 0, 0, 0);
        resOutL[rp] = make_uint4(0, 0, 0, 0);
    }
}

// ---------------- skip transpose [b][t][c] -> [b][c][t] -------------------
__global__ void transpose_skip() {
    __shared__ float tile[32][33];
    int b  = blockIdx.z;
    int c0 = blockIdx.y * 32;
    int t0 = blockIdx.x * 32;
    int tx = threadIdx.x, ty = threadIdx.y;   // (32, 8)
    #pragma unroll
    for (int k = 0; k < 4; k++) {
        int c = c0 + tx, t = t0 + ty + k * 8;
        tile[ty + k * 8][tx] = (c < SC) ? g_skip[((size_t)b * TLEN + t) * SC + c] : 0.f;
    }
    __syncthreads();
    #pragma unroll
    for (int k = 0; k < 4; k++) {
        int c = c0 + ty + k * 8, t = t0 + tx;
        if (c < SC) g_skipT[((size_t)b * SC + c) * TLEN + t] = tile[tx][ty + k * 8];
    }
}

// ---------------- fp32 head kernels (proven v2 structure) -----------------
__global__ void __launch_bounds__(256, 2) final1_kernel(
    const float* __restrict__ out_b)
{
    __shared__ float Ws[8 * 256];
    __shared__ float Bs[8 * 64];
    const int tid = threadIdx.x;
    const int tx = tid & 15, ty = tid >> 4;
    const int t0 = blockIdx.x * 64;
    const int b  = blockIdx.y;

    float acc[16][4];
    #pragma unroll
    for (int j = 0; j < 16; j++) {
        float bv = out_b[ty + 16 * j];
        #pragma unroll
        for (int m = 0; m < 4; m++) acc[j][m] = bv;
    }
    for (int kc = 0; kc < 30; kc++) {
        int kb = kc * 8;
        __syncthreads();
        for (int e = tid; e < 8 * 64; e += 256) {
            int kk = e >> 6, tt = e & 63;
            float v = g_skipT[((size_t)b * SC + kb + kk) * TLEN + t0 + tt];
            Bs[e] = fmaxf(v, 0.f);
        }
        for (int e = tid; e < 8 * 256; e += 256) Ws[e] = g_Wo[kb * 256 + e];
        __syncthreads();
        #pragma unroll
        for (int kk = 0; kk < 8; kk++) {
            float a0 = Bs[kk * 64 + tx];
            float a1 = Bs[kk * 64 + tx + 16];
            float a2 = Bs[kk * 64 + tx + 32];
            float a3 = Bs[kk * 64 + tx + 48];
            const float* wr = &Ws[kk * 256 + ty];
            #pragma unroll
            for (int j = 0; j < 16; j++) {
                float w = wr[16 * j];
                acc[j][0] += w * a0; acc[j][1] += w * a1;
                acc[j][2] += w * a2; acc[j][3] += w * a3;
            }
        }
    }
    #pragma unroll
    for (int j = 0; j < 16; j++) {
        int o = ty + 16 * j;
        #pragma unroll
        for (int m = 0; m < 4; m++)
            g_o[((size_t)b * NC + o) * TLEN + t0 + tx + 16 * m] = acc[j][m];
    }
}

__global__ void __launch_bounds__(256, 2) final2_kernel(
    const float* __restrict__ end_b, float* __restrict__ out)
{
    __shared__ float Ws[8 * 256];
    __shared__ float Bs[8 * 64];
    const int tid = threadIdx.x;
    const int tx = tid & 15, ty = tid >> 4;
    const int t0 = blockIdx.x * 64;
    const int b  = blockIdx.y;

    float acc[16][4];
    #pragma unroll
    for (int j = 0; j < 16; j++) {
        float bv = end_b[ty + 16 * j];
        #pragma unroll
        for (int m = 0; m < 4; m++) acc[j][m] = bv;
    }
    for (int kc = 0; kc < 32; kc++) {
        int kb = kc * 8;
        __syncthreads();
        for (int e = tid; e < 8 * 64; e += 256) {
            int kk = e >> 6, tt = e & 63;
            float v = g_o[((size_t)b * NC + kb + kk) * TLEN + t0 + tt];
            Bs[e] = fmaxf(v, 0.f);
        }
        for (int e = tid; e < 8 * 256; e += 256) Ws[e] = g_We[kb * 256 + e];
        __syncthreads();
        #pragma unroll
        for (int kk = 0; kk < 8; kk++) {
            float a0 = Bs[kk * 64 + tx];
            float a1 = Bs[kk * 64 + tx + 16];
            float a2 = Bs[kk * 64 + tx + 32];
            float a3 = Bs[kk * 64 + tx + 48];
            const float* wr = &Ws[kk * 256 + ty];
            #pragma unroll
            for (int j = 0; j < 16; j++) {
                float w = wr[16 * j];
                acc[j][0] += w * a0; acc[j][1] += w * a1;
                acc[j][2] += w * a2; acc[j][3] += w * a3;
            }
        }
    }
    #pragma unroll
    for (int j = 0; j < 16; j++) {
        int o = ty + 16 * j;
        #pragma unroll
        for (int m = 0; m < 4; m++)
            out[((size_t)b * NC + o) * TLEN + t0 + tx + 16 * m] = acc[j][m];
    }
}

// ---------------- host launcher -------------------------------------------
extern "C" void kernel_launch(void* const* d_in, const int* in_sizes, int n_in,
                              void* d_out, int out_size) {
    const float* wav    = (const float*)d_in[0];
    const float* cond   = (const float*)d_in[1];
    const float* wav_w  = (const float*)d_in[2];
    const float* wav_b  = (const float*)d_in[3];
    const float* cond_w = (const float*)d_in[4];
    const float* cond_b = (const float*)d_in[5];
    const float* dil_w  = (const float*)d_in[6];
    const float* dil_b  = (const float*)d_in[7];
    const float* skip_w = (const float*)d_in[8];
    const float* skip_b = (const float*)d_in[9];
    const float* res_w  = (const float*)d_in[10];
    const float* res_b  = (const float*)d_in[11];
    const float* out_w  = (const float*)d_in[12];
    const float* out_b  = (const float*)d_in[13];
    const float* end_w  = (const float*)d_in[14];
    const float* end_b  = (const float*)d_in[15];

    cudaFuncSetAttribute(block_mma, cudaFuncAttributeMaxDynamicSharedMemorySize,
                         SMEM_MMA);

    repack_w1<<<(NBLK * 6 * 240 * 64 + 255) / 256, 256>>>(dil_w, cond_w);
    repack_w2<<<(NBLK * 2 * (240 + 120) * 64 + 255) / 256, 256>>>(skip_w, res_w);
    repack_wf<<<(240 * 256 + 256 * 256 + 255) / 256, 256>>>(out_w, end_w);
    prologue_res<<<(BB * TLEN * 16 + 255) / 256, 256>>>(wav, wav_w, wav_b);
    prologue_cond<<<(BB * TLEN * 16 + 255) / 256, 256>>>(cond);

    dim3 gridB(TLEN / 128, BB);
    for (int i = 0; i < NBLK; i++) {
        int d = 1 << (i % 8);
        block_mma<<<gridB, 256, SMEM_MMA>>>(dil_b, cond_b, skip_b, res_b,
                                            i, d, (i == 0) ? 1 : 0, i & 1);
    }
    dim3 gridT(TLEN / 32, 8, BB);
    transpose_skip<<<gridT, dim3(32, 8)>>>();
    dim3 gridH(TLEN / 64, BB);
    final1_kernel<<<gridH, 256>>>(out_b);
    final2_kernel<<<gridH, 256>>>(end_b, (float*)d_out);
}